// round 7
// baseline (speedup 1.0000x reference)
#include <cuda_runtime.h>

#define NN 512          // T = U = 512
#define NT 256          // 256 threads, 2 interleaved columns each, 8 warps
#define C_CONST 1.0f
#define GEPS 1e-9f
#define MAXB 64

__device__ float g_costs[MAXB];
__device__ int g_ctr = 0;

// Fence-free handoff: tag+value packed in ONE 64-bit shared word (8B store is
// atomic), so plain volatile accesses suffice — no release/acquire, no MEMBAR.
__device__ __forceinline__ void st_vol64(unsigned long long* p, unsigned long long v) {
    unsigned a = (unsigned)__cvta_generic_to_shared(p);
    asm volatile("st.volatile.shared.b64 [%0], %1;" :: "r"(a), "l"(v) : "memory");
}
__device__ __forceinline__ unsigned long long ld_vol64(unsigned long long* p) {
    unsigned a = (unsigned)__cvta_generic_to_shared(p);
    unsigned long long v;
    asm volatile("ld.volatile.shared.b64 %0, [%1];" : "=l"(v) : "r"(a) : "memory");
    return v;
}

// trans with a, b given plus precomputed A=a^2, B=b^2 (B shared with match)
__device__ __forceinline__ float transf(float a, float b, float A, float B) {
    float u = a * b;
    float w = 0.5f * (1.0f + u * rsqrtf(fmaf(u, u, GEPS)));   // 1 - gate
    float mn = fminf(A, B);
    float mx = fmaxf(A, B);
    float sm = mn - __logf(1.0f + __expf(mn - mx));           // softmin2
    return fmaf(w, sm, C_CONST);
}

// softmin3 with the min-arm's exp folded to 1 (exact), INF-safe for boundary arms
__device__ __forceinline__ float softmin3f(float a, float b, float c) {
    float mn    = fminf(a, fminf(b, c));
    float mx    = fmaxf(a, fmaxf(b, c));
    float ab_mn = fminf(a, b);
    float ab_mx = fmaxf(a, b);
    float md    = fmaxf(ab_mn, fminf(ab_mx, c));              // median
    float s = 1.0f + __expf(mn - md) + __expf(mn - mx);       // exp(mn-mn)==1
    return mn - __logf(s);
}

__global__ __launch_bounds__(NT, 1)
void soft_msm_kernel(const float* __restrict__ x, const float* __restrict__ y,
                     float* __restrict__ out, int B) {
    __shared__ float sxe[NT], sxo[NT];            // x even / odd indices
    __shared__ float saue[NT], sauo[NT];          // x[i]-x[i-1], split by parity of i
    __shared__ unsigned long long bnd[7][512];    // (tag<<32 | valbits) boundary handoff rings

    const int b    = blockIdx.x;
    const int t    = threadIdx.x;
    const int w    = t >> 5;
    const int lane = t & 31;
    const float* xb = x + b * NN;
    const float* yb = y + b * NN;

    // column constants: jE = 2t, jO = 2t+1
    const float yE   = yb[2 * t];
    const float yO   = yb[2 * t + 1];
    const float yEm1 = (t > 0) ? yb[2 * t - 1] : 0.0f;
    const float alE  = yE - yEm1;
    const float alO  = yO - yE;
    const float alE2 = alE * alE;
    const float alO2 = alO * alO;

    const float xe = xb[2 * t];
    const float xo = xb[2 * t + 1];
    sxe[t] = xe; sxo[t] = xo;

    // init boundary ring tags to -1
    for (int i = t; i < 7 * 512; i += NT)
        ((unsigned long long*)bnd)[i] = 0xFFFFFFFF00000000ull;
    __syncthreads();
    saue[t] = (t > 0) ? (xe - sxo[t - 1]) : 0.0f;   // sau[2t]
    sauo[t] = xo - xe;                               // sau[2t+1]
    const float x0 = sxe[0];
    __syncthreads();

    // carried DP state
    float prevE  = 0.0f;   // C[.., jE] @ d-1
    float prevO  = 0.0f;   // C[.., jO] @ d-1
    float prev2E = 0.0f;   // C[.., jE] @ d-2  (diag for odd cell)
    float pdiagE = 0.0f;   // C[.., jE-1] @ d-2 (diag for even cell)
    if (t == 0) { float d0 = x0 - yE; prevE = d0 * d0; }     // C[0,0], diagonal 0

    const int jE = 2 * t;
    const float INF = __int_as_float(0x7f800000);

    const int D0     = 64 * w;
    const int dStart = (w == 0) ? 1 : D0;
    const int dEnd   = D0 + 574;          // warp 7 ends at 1022

    for (int d = dStart; d <= dEnd; ++d) {
        // left neighbor of even col on diagonal d-1 = prev thread's odd col
        float fromLeft = __shfl_up_sync(0xffffffffu, prevO, 1);
        if (lane == 0 && w > 0 && d <= D0 + 511) {
            // producer (warp w-1) wrote diag d-1 into slot (d-1)&511, tag = d-1
            unsigned long long pk = ld_vol64(&bnd[w - 1][(d - 1) & 511]);
            while ((int)(pk >> 32) != d - 1) {
                pk = ld_vol64(&bnd[w - 1][(d - 1) & 511]);
            }
            fromLeft = __uint_as_float((unsigned)pk);
        }

        // parity-split x arrays: parity(iE) == parity(d)
        const float* xEa = (d & 1) ? sxo  : sxe;
        const float* xOa = (d & 1) ? sxe  : sxo;
        const float* sEa = (d & 1) ? sauo : saue;
        const float* sOa = (d & 1) ? saue : sauo;

        const int iE = d - jE;
        const int iO = iE - 1;
        const bool vE = (iE >= 0) && (iE < NN);
        const bool vO = (iO >= 0) && (iO < NN);
        const int iEc = min(max(iE, 0), NN - 1);
        const int iOc = min(max(iO, 0), NN - 1);
        const float xiE = xEa[iEc >> 1];
        const float xiO = xOa[iOc >> 1];
        const float saE = sEa[iEc >> 1];
        const float saO = sOa[iOc >> 1];

        // ---- even cell (iE, jE) ----
        float bxE = xiE - yE;
        float mE  = bxE * bxE;
        float utE = transf(saE,  bxE, saE * saE, mE);   // trans(x_i, x_{i-1}, y_j)
        float ltE = transf(alE, -bxE, alE2,      mE);   // trans(y_j, y_{j-1}, x_i)
        float dd = pdiagE   + mE;
        float du = prevE    + utE;
        float cl = fromLeft + ltE;
        if (jE == 0) { dd = INF; cl = INF; }            // col-0 boundary
        if (iE == 0) { dd = INF; du = INF; }            // row-0 boundary
        float cE = softmin3f(dd, du, cl);

        // ---- odd cell (iO, jO): neighbors are own registers ----
        float bxO = xiO - yO;
        float mO  = bxO * bxO;
        float utO = transf(saO,  bxO, saO * saO, mO);
        float ltO = transf(alO, -bxO, alO2,      mO);
        float ddo = prev2E + mO;
        float duo = prevO  + utO;
        float clo = prevE  + ltO;                       // left = even col @ d-1
        if (iO == 0) { ddo = INF; duo = INF; }
        float cO = softmin3f(ddo, duo, clo);

        // state rotation (compute-then-update; predicated on validity)
        if (vE) { pdiagE = fromLeft; prev2E = prevE; prevE = cE; }
        if (vO) {
            prevO = cO;
            if (lane == 31 && w < 7)
                st_vol64(&bnd[w][d & 511],
                         ((unsigned long long)(unsigned)d << 32) |
                         (unsigned long long)__float_as_uint(cO));
        }
    }

    // fused mean-reduction: last CTA to arrive sums and writes out
    if (t == NT - 1) {
        g_costs[b] = prevO;                 // C[511,511]
        __threadfence();
        int old = atomicAdd(&g_ctr, 1);
        if (old == B - 1) {
            __threadfence();
            float s = 0.0f;
            for (int i = 0; i < B; ++i)
                s += *((volatile float*)&g_costs[i]);
            out[0] = s * (1.0f / (float)B);
            atomicExch(&g_ctr, 0);          // reset for next graph replay
        }
    }
}

extern "C" void kernel_launch(void* const* d_in, const int* in_sizes, int n_in,
                              void* d_out, int out_size) {
    const float* x = (const float*)d_in[0];
    const float* y = (const float*)d_in[1];
    int B = in_sizes[0] / NN;   // 64
    if (B > MAXB) B = MAXB;
    soft_msm_kernel<<<B, NT>>>(x, y, (float*)d_out, B);
}

// round 8
// speedup vs baseline: 1.3317x; 1.3317x over previous
#include <cuda_runtime.h>

#define NN 512          // T = U = 512
#define NT 256          // threads per CTA; 8 warps, 1 column/thread, 256 cols/CTA
#define C_CONST 1.0f
#define GEPS 1e-9f
#define MAXB 64

__device__ float g_costs[MAXB];
__device__ int g_ctr = 0;
// inter-CTA boundary ring: one slot per diagonal (no wraparound). (tag<<32)|valbits.
__device__ unsigned long long g_bnd[MAXB][1024];

// ---- fence-free 8B tag|value handoffs (8B accesses are single-copy atomic) ----
__device__ __forceinline__ void sts_vol64(unsigned long long* p, unsigned long long v) {
    unsigned a = (unsigned)__cvta_generic_to_shared(p);
    asm volatile("st.volatile.shared.b64 [%0], %1;" :: "r"(a), "l"(v) : "memory");
}
__device__ __forceinline__ unsigned long long lds_vol64(unsigned long long* p) {
    unsigned a = (unsigned)__cvta_generic_to_shared(p);
    unsigned long long v;
    asm volatile("ld.volatile.shared.b64 %0, [%1];" : "=l"(v) : "r"(a) : "memory");
    return v;
}
__device__ __forceinline__ void stg_vol64(unsigned long long* p, unsigned long long v) {
    asm volatile("st.volatile.global.b64 [%0], %1;" :: "l"(p), "l"(v) : "memory");
}
__device__ __forceinline__ unsigned long long ldg_vol64(const unsigned long long* p) {
    unsigned long long v;
    asm volatile("ld.volatile.global.b64 %0, [%1];" : "=l"(v) : "l"(p) : "memory");
    return v;
}

// trans with precomputed A=a^2, B=b^2 (B shared with match)
__device__ __forceinline__ float transf(float a, float b, float A, float B) {
    float u = a * b;
    float w = 0.5f * (1.0f + u * rsqrtf(fmaf(u, u, GEPS)));   // 1 - gate
    float mn = fminf(A, B);
    float mx = fmaxf(A, B);
    float sm = mn - __logf(1.0f + __expf(mn - mx));           // softmin2
    return fmaf(w, sm, C_CONST);
}

// softmin3, min-arm exp folded to 1; INF-safe for boundary arms
__device__ __forceinline__ float softmin3f(float a, float b, float c) {
    float mn    = fminf(a, fminf(b, c));
    float mx    = fmaxf(a, fmaxf(b, c));
    float ab_mn = fminf(a, b);
    float ab_mx = fmaxf(a, b);
    float md    = fmaxf(ab_mn, fminf(ab_mx, c));              // median
    float s = 1.0f + __expf(mn - md) + __expf(mn - mx);
    return mn - __logf(s);
}

__global__ __launch_bounds__(NT, 1)
void soft_msm_kernel(const float* __restrict__ x, const float* __restrict__ y,
                     float* __restrict__ out, int B) {
    __shared__ float sx[NN], sau[NN];             // full x and x[i]-x[i-1]
    __shared__ unsigned long long bnd[7][512];    // intra-CTA boundary rings

    const int blk  = blockIdx.x;
    const int b    = blk >> 1;            // batch
    const int half = blk & 1;             // 0: cols 0..255, 1: cols 256..511
    const int t    = threadIdx.x;
    const int w    = t >> 5;
    const int lane = t & 31;
    const int j    = half * 256 + t;      // global column owned by this thread

    const float* xb = x + b * NN;
    const float* yb = y + b * NN;

    const float yj  = yb[j];
    const float al  = (j > 0) ? (yj - yb[j - 1]) : 0.0f;   // y_j - y_{j-1}
    const float al2 = al * al;

    sx[t]       = xb[t];
    sx[t + 256] = xb[t + 256];
    // init smem ring tags to invalid
    #pragma unroll
    for (int r = 0; r < 7 * 512 / NT; ++r)
        ((unsigned long long*)bnd)[t + r * NT] = 0xFFFFFFFF00000000ull;
    __syncthreads();
    sau[t]       = (t > 0) ? (sx[t] - sx[t - 1]) : 0.0f;
    sau[t + 256] = sx[t + 256] - sx[t + 255];
    __syncthreads();

    float curC  = 0.0f;   // C[i-1, j]   (own value, previous diagonal)
    float pdiag = 0.0f;   // C[i-1, j-1] (left value, two diagonals back)
    if (half == 0 && t == 0) { float d0 = sx[0] - yj; curC = d0 * d0; }   // C[0,0]

    const float INF = __int_as_float(0x7f800000);
    const int base = half * 256 + 32 * w;        // first diagonal this warp touches
    const int dEnd = base + 542;                 // lane31 last valid diag
    const bool globalConsumer = (half == 1) && (w == 0);
    const bool globalProducer = (half == 0) && (w == 7);

    // consumer queue state (warp-uniform; used only by globalConsumer warp)
    float qval = 0.0f;
    int qcount = 0, qpos = 0;

    for (int d = (base == 0 ? 1 : base); d <= dEnd; ++d) {
        float fromLeft = __shfl_up_sync(0xffffffffu, curC, 1);

        if (d <= base + 511) {                   // lane-0 cell still live
            if (globalConsumer) {
                // warp-cooperative batched refill from the inter-CTA ring
                if (qpos >= qcount) {
                    const int qbase = d - 1;
                    unsigned long long pk;
                    for (;;) {
                        pk = ldg_vol64(&g_bnd[b][qbase + lane]);   // qbase+31 <= 797 < 1024
                        unsigned ball = __ballot_sync(0xffffffffu,
                                                      (int)(pk >> 32) == qbase + lane);
                        qcount = (ball == 0xffffffffu) ? 32 : (__ffs(~ball) - 1);
                        if (qcount > 0) break;
                    }
                    qval = __uint_as_float((unsigned)pk);
                    qpos = 0;
                }
                float bl = __shfl_sync(0xffffffffu, qval, qpos);
                qpos++;
                if (lane == 0) fromLeft = bl;
            } else if (w > 0 && lane == 0) {
                unsigned long long pk = lds_vol64(&bnd[w - 1][(d - 1) & 511]);
                while ((int)(pk >> 32) != d - 1)
                    pk = lds_vol64(&bnd[w - 1][(d - 1) & 511]);
                fromLeft = __uint_as_float((unsigned)pk);
            }
        }

        const int  i  = d - j;
        const bool v  = (i >= 0) && (i < NN);
        const int  ic = min(max(i, 0), NN - 1);
        const float xi = sx[ic];
        const float sa = sau[ic];

        float bx = xi - yj;
        float m  = bx * bx;
        float ut = transf(sa,  bx, sa * sa, m);   // trans(x_i, x_{i-1}, y_j)
        float lt = transf(al, -bx, al2,     m);   // trans(y_j, y_{j-1}, x_i)
        float dd = pdiag    + m;
        float du = curC     + ut;
        float cl = fromLeft + lt;
        if (j == 0) { dd = INF; cl = INF; }       // col-0 boundary
        if (i == 0) { dd = INF; du = INF; }       // row-0 boundary
        float c = softmin3f(dd, du, cl);

        if (v) {
            pdiag = fromLeft;
            curC  = c;
            if (lane == 31) {
                unsigned long long pk =
                    ((unsigned long long)(unsigned)d << 32) |
                    (unsigned long long)__float_as_uint(c);
                if (w < 7)              sts_vol64(&bnd[w][d & 511], pk);
                else if (globalProducer) stg_vol64(&g_bnd[b][d], pk);
            }
        }
    }

    // fused mean-reduction: last finishing half-1 CTA sums and writes out
    if (half == 1 && t == NT - 1) {
        g_costs[b] = curC;                 // C[511,511]
        __threadfence();
        int old = atomicAdd(&g_ctr, 1);
        if (old == B - 1) {
            __threadfence();
            float s = 0.0f;
            for (int i2 = 0; i2 < B; ++i2)
                s += *((volatile float*)&g_costs[i2]);
            out[0] = s * (1.0f / (float)B);
            atomicExch(&g_ctr, 0);         // reset for next graph replay
        }
    }
}

extern "C" void kernel_launch(void* const* d_in, const int* in_sizes, int n_in,
                              void* d_out, int out_size) {
    const float* x = (const float*)d_in[0];
    const float* y = (const float*)d_in[1];
    int B = in_sizes[0] / NN;   // 64
    if (B > MAXB) B = MAXB;
    soft_msm_kernel<<<2 * B, NT>>>(x, y, (float*)d_out, B);
}

// round 10
// speedup vs baseline: 1.4331x; 1.0762x over previous
#include <cuda_runtime.h>

#define NN 512          // T = U = 512
#define NT 256          // 8 warps, 1 column/thread, 256 cols per CTA, 2 CTAs/batch
#define C_CONST 1.0f
#define GEPS 1e-9f
#define MAXB 64

__device__ float g_costs[MAXB];
__device__ int g_ctr = 0;
// inter-CTA boundary ring: one slot per diagonal (no wraparound). (tag<<32)|valbits.
__device__ unsigned long long g_bnd[MAXB][1024];

// ---- fence-free 8B tag|value handoffs (8B accesses are single-copy atomic) ----
__device__ __forceinline__ void sts_vol64(unsigned long long* p, unsigned long long v) {
    unsigned a = (unsigned)__cvta_generic_to_shared(p);
    asm volatile("st.volatile.shared.b64 [%0], %1;" :: "r"(a), "l"(v) : "memory");
}
__device__ __forceinline__ unsigned long long lds_vol64(unsigned long long* p) {
    unsigned a = (unsigned)__cvta_generic_to_shared(p);
    unsigned long long v;
    asm volatile("ld.volatile.shared.b64 %0, [%1];" : "=l"(v) : "r"(a) : "memory");
    return v;
}
__device__ __forceinline__ void stg_vol64(unsigned long long* p, unsigned long long v) {
    asm volatile("st.volatile.global.b64 [%0], %1;" :: "l"(p), "l"(v) : "memory");
}
__device__ __forceinline__ unsigned long long ldg_vol64(const unsigned long long* p) {
    unsigned long long v;
    asm volatile("ld.volatile.global.b64 %0, [%1];" : "=l"(v) : "l"(p) : "memory");
    return v;
}

__device__ __forceinline__ float transf(float a, float b, float A, float B) {
    float u = a * b;
    float w = 0.5f * (1.0f + u * rsqrtf(fmaf(u, u, GEPS)));   // 1 - gate
    float mn = fminf(A, B);
    float mx = fmaxf(A, B);
    float sm = mn - __logf(1.0f + __expf(mn - mx));           // softmin2
    return fmaf(w, sm, C_CONST);
}

// softmin3, min-arm exp folded to 1; INF-safe for boundary arms
__device__ __forceinline__ float softmin3f(float a, float b, float c) {
    float mn    = fminf(a, fminf(b, c));
    float mx    = fmaxf(a, fmaxf(b, c));
    float ab_mn = fminf(a, b);
    float ab_mx = fmaxf(a, b);
    float md    = fmaxf(ab_mn, fminf(ab_mx, c));              // median
    float s = 1.0f + __expf(mn - md) + __expf(mn - mx);
    return mn - __logf(s);
}

__global__ __launch_bounds__(NT, 1)
void soft_msm_kernel(const float* __restrict__ x, const float* __restrict__ y,
                     float* __restrict__ out, int B) {
    __shared__ float4 sq[NN];                     // (x_i, sau_i, sau_i^2, 0)
    __shared__ unsigned long long bnd[7][512];    // intra-CTA boundary rings

    const int blk  = blockIdx.x;
    const int b    = blk >> 1;
    const int half = blk & 1;             // 0: cols 0..255, 1: cols 256..511
    const int t    = threadIdx.x;
    const int w    = t >> 5;
    const int lane = t & 31;
    const int jme  = half * 256 + t;      // my column
    const int j0   = half * 256 + 32 * w; // lane0's column in this warp

    const float* xb = x + b * NN;
    const float* yb = y + b * NN;

    const float yj  = yb[jme];
    const float al  = (jme > 0) ? (yj - yb[jme - 1]) : 0.0f;
    const float al2 = al * al;

    sq[t].x       = xb[t];
    sq[t + 256].x = xb[t + 256];
    #pragma unroll
    for (int r = 0; r < 7 * 512 / NT; ++r)
        ((unsigned long long*)bnd)[t + r * NT] = 0xFFFFFFFF00000000ull;
    __syncthreads();
    {
        float x1 = sq[t].x;
        float s1 = (t > 0) ? (x1 - sq[t - 1].x) : 0.0f;
        float x2 = sq[t + 256].x;
        float s2 = x2 - sq[t + 255].x;
        sq[t].y = s1;        sq[t].z = s1 * s1;
        sq[t + 256].y = s2;  sq[t + 256].z = s2 * s2;
    }
    __syncthreads();

    const float INF = __int_as_float(0x7f800000);
    const bool leftINF = (half == 0) && (w == 0);    // no producer; col-0 boundary
    const bool gCons   = (half == 1) && (w == 0);    // consumes inter-CTA ring
    const bool gProd   = (half == 0) && (w == 7);    // produces inter-CTA ring

    float curC  = 0.0f;
    float pdiag = 0.0f;
    if (half == 0 && t == 0) { float d0 = sq[0].x - yj; curC = d0 * d0; }  // C[0,0]

    // ================= HEAD: d in [dstart, j0+31], generic body =================
    {
        const int dstart = leftINF ? 1 : j0;
        for (int d = dstart; d <= j0 + 31; ++d) {
            float fl = __shfl_up_sync(0xffffffffu, curC, 1);
            if (lane == 0) {
                if (leftINF) fl = INF;
                else if (gCons) {
                    unsigned long long pk = ldg_vol64(&g_bnd[b][d - 1]);
                    while ((int)(pk >> 32) != d - 1) pk = ldg_vol64(&g_bnd[b][d - 1]);
                    fl = __uint_as_float((unsigned)pk);
                } else {
                    unsigned long long pk = lds_vol64(&bnd[w - 1][(d - 1) & 511]);
                    while ((int)(pk >> 32) != d - 1) pk = lds_vol64(&bnd[w - 1][(d - 1) & 511]);
                    fl = __uint_as_float((unsigned)pk);
                }
            }
            const int  i = d - jme;
            const bool v = (i >= 0);
            float4 q = sq[i & 511];
            float bx = q.x - yj;
            float m  = bx * bx;
            float ut = transf(q.y, bx, q.z, m);
            float lt = transf(al, -bx, al2, m);
            float dd = pdiag + m;
            float du = curC  + ut;
            float cl = fl    + lt;
            if (jme == 0) { dd = INF; cl = INF; }
            if (i == 0)   { dd = INF; du = INF; }
            float c = softmin3f(dd, du, cl);
            if (v) {
                pdiag = fl; curC = c;
                if (lane == 31) {
                    unsigned long long pk = ((unsigned long long)(unsigned)d << 32) |
                                            (unsigned long long)__float_as_uint(c);
                    if (w < 7) sts_vol64(&bnd[w][d & 511], pk);
                    else if (gProd) stg_vol64(&g_bnd[b][d], pk);
                }
            }
        }
    }

    // ============ STEADY: d in [j0+32, j0+511], lean body, all lanes valid ============
    {
        float qval = 0.0f; int qcnt = 0, qpos = 0;   // gCons batched queue

        // preamble: fromLeft for d = j0+32 (needs slot j0+31)
        float fl = __shfl_up_sync(0xffffffffu, curC, 1);
        if (leftINF) {
            if (lane == 0) fl = INF;
        } else if (gCons) {
            const int qb = j0 + 31;
            unsigned long long pk;
            for (;;) {
                pk = ldg_vol64(&g_bnd[b][qb + lane]);
                unsigned ball = __ballot_sync(0xffffffffu, (int)(pk >> 32) == qb + lane);
                qcnt = (ball == 0xffffffffu) ? 32 : (__ffs(~ball) - 1);
                if (qcnt > 0) break;
            }
            qval = __uint_as_float((unsigned)pk);
            float qv0 = __shfl_sync(0xffffffffu, qval, 0);
            qpos = 1;
            if (lane == 0) fl = qv0;
        } else {
            unsigned long long pk = lds_vol64(&bnd[w - 1][(j0 + 31) & 511]);
            while ((int)(pk >> 32) != j0 + 31) pk = lds_vol64(&bnd[w - 1][(j0 + 31) & 511]);
            if (lane == 0) fl = __uint_as_float((unsigned)pk);
        }

        #pragma unroll 2
        for (int d = j0 + 32; d <= j0 + 511; ++d) {
            const int i = d - jme;                 // 1..511, always interior
            float4 q = sq[i];
            float bx = q.x - yj;
            float m  = bx * bx;
            float ut = transf(q.y, bx, q.z, m);
            float lt = transf(al, -bx, al2, m);
            float dd = pdiag + m;
            float du = curC  + ut;
            float cl = fl    + lt;
            float c  = softmin3f(dd, du, cl);      // INF arms (leftINF lane0) absorbed exactly
            pdiag = fl;
            curC  = c;

            // produce (lane31 always valid here)
            if (w < 7) {
                if (lane == 31)
                    sts_vol64(&bnd[w][d & 511],
                              ((unsigned long long)(unsigned)d << 32) |
                              (unsigned long long)__float_as_uint(c));
            } else if (gProd) {
                if (lane == 31)
                    stg_vol64(&g_bnd[b][d],
                              ((unsigned long long)(unsigned)d << 32) |
                              (unsigned long long)__float_as_uint(c));
            }

            // fromLeft for next iteration (poll-ahead, off the critical chain)
            fl = __shfl_up_sync(0xffffffffu, c, 1);
            if (d <= j0 + 510) {
                if (leftINF) {
                    if (lane == 0) fl = INF;
                } else if (gCons) {
                    if (qpos >= qcnt) {
                        unsigned long long pk;
                        for (;;) {
                            pk = ldg_vol64(&g_bnd[b][d + lane]);
                            unsigned ball = __ballot_sync(0xffffffffu,
                                                          (int)(pk >> 32) == d + lane);
                            qcnt = (ball == 0xffffffffu) ? 32 : (__ffs(~ball) - 1);
                            if (qcnt > 0) break;
                        }
                        qval = __uint_as_float((unsigned)pk);
                        qpos = 0;
                    }
                    float qvv = __shfl_sync(0xffffffffu, qval, qpos);
                    qpos++;
                    if (lane == 0) fl = qvv;
                } else {
                    // warp-uniform broadcast poll of slot d
                    unsigned long long pk = lds_vol64(&bnd[w - 1][d & 511]);
                    while ((int)(pk >> 32) != d) pk = lds_vol64(&bnd[w - 1][d & 511]);
                    if (lane == 0) fl = __uint_as_float((unsigned)pk);
                }
            }
        }
    }

    // ================= TAIL: d in [j0+512, j0+542], generic body =================
    for (int d = j0 + 512; d <= j0 + 542; ++d) {
        float fl = __shfl_up_sync(0xffffffffu, curC, 1);   // no consume: lane0 inactive
        const int  i = d - jme;                            // >= 1
        const bool v = (i < NN);
        float4 q = sq[i & 511];
        float bx = q.x - yj;
        float m  = bx * bx;
        float ut = transf(q.y, bx, q.z, m);
        float lt = transf(al, -bx, al2, m);
        float dd = pdiag + m;
        float du = curC  + ut;
        float cl = fl    + lt;
        float c  = softmin3f(dd, du, cl);
        if (v) {
            pdiag = fl; curC = c;
            if (lane == 31) {
                unsigned long long pk = ((unsigned long long)(unsigned)d << 32) |
                                        (unsigned long long)__float_as_uint(c);
                if (w < 7) sts_vol64(&bnd[w][d & 511], pk);
                else if (gProd) stg_vol64(&g_bnd[b][d], pk);
            }
        }
    }

    // fused mean-reduction: last finishing half-1 CTA sums and writes out
    if (half == 1 && t == NT - 1) {
        g_costs[b] = curC;                 // C[511,511]
        __threadfence();
        int old = atomicAdd(&g_ctr, 1);
        if (old == B - 1) {
            __threadfence();
            float s = 0.0f;
            for (int i2 = 0; i2 < B; ++i2)
                s += *((volatile float*)&g_costs[i2]);
            out[0] = s * (1.0f / (float)B);
            atomicExch(&g_ctr, 0);         // reset for next graph replay
        }
    }
}

extern "C" void kernel_launch(void* const* d_in, const int* in_sizes, int n_in,
                              void* d_out, int out_size) {
    const float* x = (const float*)d_in[0];
    const float* y = (const float*)d_in[1];
    int B = in_sizes[0] / NN;   // 64
    if (B > MAXB) B = MAXB;
    soft_msm_kernel<<<2 * B, NT>>>(x, y, (float*)d_out, B);
}